// round 12
// baseline (speedup 1.0000x reference)
#include <cuda_runtime.h>
#include <cuda_bf16.h>

// Fixed problem shapes
#define IMG_H 544
#define IMG_W 960
#define OUT_H 136
#define OUT_W 240

// Each WARP produces a 30x4 output strip (120x16 mag region) by streaming
// 22 input rows with all intermediates in registers (no shared memory).
// prefetch.global.L2 runs 2 iterations ahead of the LDG consume so the
// load hits L2 (~250cyc) instead of DRAM (~600cyc) -- zero register cost.
#define TW 30

// Normalized 1D Gaussian, k=5, sigma=1.5
#define GW0 0.120078385f
#define GW1 0.233880757f
#define GW2 0.292081718f

__device__ __forceinline__ int reflect_idx(int i, int n) {
    if (i < 0) i = -i;
    if (i >= n) i = 2 * n - 2 - i;
    return i;
}

__device__ __forceinline__ float sqrt_approx(float x) {
    float r;
    asm("sqrt.approx.f32 %0, %1;" : "=f"(r) : "f"(x));
    return r;
}

__device__ __forceinline__ void pf_l2(const float* p) {
    asm volatile("prefetch.global.L2 [%0];" :: "l"(p));
}

__global__ __launch_bounds__(128, 8)
void EdgeGuidance_47313359733145_kernel(const float* __restrict__ in,
                                        float* __restrict__ out)
{
    const int lane = threadIdx.x & 31;
    const int wid  = threadIdx.x >> 5;
    const int ct   = blockIdx.x * 4 + wid;   // column tile 0..7  (30 out cols each)
    const int by   = blockIdx.y;             // row strip 0..33   (4 out rows each)
    const int b    = blockIdx.z;             // batch

    const int mx0 = ct * (TW * 4);           // mag-space x origin (120 per tile)
    const int my0 = by * 16;                 // mag-space y origin

    const float* __restrict__ pr = in + (size_t)b * 3 * IMG_H * IMG_W;
    const float* __restrict__ pg = pr + IMG_H * IMG_W;
    const float* __restrict__ pb = pg + IMG_H * IMG_W;

    // Lane's gray vec covers global x = gx0 .. gx0+3
    const int gx0 = mx0 - 4 + (lane << 2);
    const bool xfast = (gx0 >= 0) && (gx0 + 3 < IMG_W);
    const int rx0 = reflect_idx(gx0 + 0, IMG_W);
    const int rx1 = reflect_idx(gx0 + 1, IMG_W);
    const int rx2 = reflect_idx(gx0 + 2, IMG_W);
    const int rx3 = reflect_idx(gx0 + 3, IMG_W);

    // gs vec of this lane covers global x = gsx .. gsx+3
    const int gsx = mx0 - 1 + (lane << 2);
    const bool vx0 = (gsx + 0 >= 0) && (gsx + 0 < IMG_W);
    const bool vx1 = (gsx + 1 >= 0) && (gsx + 1 < IMG_W);
    const bool vx2 = (gsx + 2 < IMG_W);
    const bool vx3 = (gsx + 3 < IMG_W);

    const unsigned FULL = 0xffffffffu;

    // L2 prefetch for input row t (global row reflect(my0-3+t)), all 3 planes.
    auto pfrow = [&](int t) {
        const int gy = reflect_idx(my0 - 3 + t, IMG_H);
        const int o = gy * IMG_W + rx0;      // rx0 == gx0 in the interior
        pf_l2(pr + o);
        pf_l2(pg + o);
        pf_l2(pb + o);
    };

    // Load + gray + horizontal blur of input row t.
    auto hbrow = [&](int t) -> float4 {
        const int gy = reflect_idx(my0 - 3 + t, IMG_H);
        const int rowoff = gy * IMG_W;
        float4 r4, g4, b4;
        if (xfast) {
            r4 = *reinterpret_cast<const float4*>(pr + rowoff + gx0);
            g4 = *reinterpret_cast<const float4*>(pg + rowoff + gx0);
            b4 = *reinterpret_cast<const float4*>(pb + rowoff + gx0);
        } else {
            r4 = make_float4(pr[rowoff + rx0], pr[rowoff + rx1], pr[rowoff + rx2], pr[rowoff + rx3]);
            g4 = make_float4(pg[rowoff + rx0], pg[rowoff + rx1], pg[rowoff + rx2], pg[rowoff + rx3]);
            b4 = make_float4(pb[rowoff + rx0], pb[rowoff + rx1], pb[rowoff + rx2], pb[rowoff + rx3]);
        }
        float4 A;
        A.x = fmaf(0.2989f, r4.x, fmaf(0.587f, g4.x, 0.114f * b4.x));
        A.y = fmaf(0.2989f, r4.y, fmaf(0.587f, g4.y, 0.114f * b4.y));
        A.z = fmaf(0.2989f, r4.z, fmaf(0.587f, g4.z, 0.114f * b4.z));
        A.w = fmaf(0.2989f, r4.w, fmaf(0.587f, g4.w, 0.114f * b4.w));

        const float Bx = __shfl_down_sync(FULL, A.x, 1);
        const float By = __shfl_down_sync(FULL, A.y, 1);
        const float Bz = __shfl_down_sync(FULL, A.z, 1);
        const float Bw = __shfl_down_sync(FULL, A.w, 1);
        const float C0 = __shfl_down_sync(FULL, A.x, 2);

        float4 o4;
        o4.x = fmaf(GW0, A.y, fmaf(GW1, A.z, fmaf(GW2, A.w, fmaf(GW1, Bx, GW0 * By))));
        o4.y = fmaf(GW0, A.z, fmaf(GW1, A.w, fmaf(GW2, Bx, fmaf(GW1, By, GW0 * Bz))));
        o4.z = fmaf(GW0, A.w, fmaf(GW1, Bx, fmaf(GW2, By, fmaf(GW1, Bz, GW0 * Bw))));
        o4.w = fmaf(GW0, Bx, fmaf(GW1, By, fmaf(GW2, Bz, fmaf(GW1, Bw, GW0 * C0))));
        return o4;
    };

    // Prologue: prefetch rows 4,5 (consumed at iters 0,1), then build hb window.
    pfrow(4); pfrow(5);
    float4 hb0 = hbrow(0);
    float4 hb1 = hbrow(1);
    float4 hb2 = hbrow(2);
    float4 hb3 = hbrow(3);

    // Rolling gs window rows (6 floats: own vec + next lane's first two)
    float w0[6], w1[6], w2[6];
    float acc = 0.0f;

    const size_t outbase = ((size_t)b * OUT_H + by * 4) * OUT_W + ct * TW + lane;

    #pragma unroll
    for (int r = 0; r < 18; ++r) {
        if (r + 6 <= 21) pfrow(r + 6);       // L2 prefetch, 2 iterations ahead

        const float4 h4 = hbrow(r + 4);      // LDG should hit L2 now

        // Vertical Gaussian -> gs row r (global gy = my0-1+r)
        float4 g;
        g.x = fmaf(GW0, hb0.x, fmaf(GW1, hb1.x, fmaf(GW2, hb2.x, fmaf(GW1, hb3.x, GW0 * h4.x))));
        g.y = fmaf(GW0, hb0.y, fmaf(GW1, hb1.y, fmaf(GW2, hb2.y, fmaf(GW1, hb3.y, GW0 * h4.y))));
        g.z = fmaf(GW0, hb0.z, fmaf(GW1, hb1.z, fmaf(GW2, hb2.z, fmaf(GW1, hb3.z, GW0 * h4.z))));
        g.w = fmaf(GW0, hb0.w, fmaf(GW1, hb1.w, fmaf(GW2, hb2.w, fmaf(GW1, hb3.w, GW0 * h4.w))));

        const int gy = my0 - 1 + r;
        const bool yok = (gy >= 0) && (gy < IMG_H);
        g.x = (yok && vx0) ? g.x : 0.0f;
        g.y = (yok && vx1) ? g.y : 0.0f;
        g.z = (yok && vx2) ? g.z : 0.0f;
        g.w = (yok && vx3) ? g.w : 0.0f;

        w2[0] = g.x; w2[1] = g.y; w2[2] = g.z; w2[3] = g.w;
        w2[4] = __shfl_down_sync(FULL, g.x, 1);
        w2[5] = __shfl_down_sync(FULL, g.y, 1);

        if (r >= 2) {
            // Sobel + magnitude for mag row m = r-2 (uses gs rows r-2, r-1, r)
            float cv[6];
            #pragma unroll
            for (int c = 0; c < 6; c++) cv[c] = w0[c] + 2.0f * w1[c] + w2[c];

            #pragma unroll
            for (int c = 1; c <= 4; c++) {
                const float sgx = cv[c + 1] - cv[c - 1];
                const float sgy = (w2[c - 1] + 2.0f * w2[c] + w2[c + 1])
                                - (w0[c - 1] + 2.0f * w0[c] + w0[c + 1]);
                acc += sqrt_approx(fmaf(sgx, sgx, fmaf(sgy, sgy, 1e-6f)));
            }

            if (((r - 2) & 3) == 3) {        // r = 5, 9, 13, 17 -> 4 output rows
                const float down = acc * (1.0f / 16.0f);
                const float e = __expf(-5.0f * (down - 0.2f));
                const float s = __fdividef(1.0f, 1.0f + e);
                if (lane < TW) {
                    out[outbase + (size_t)((r - 5) >> 2) * OUT_W] = s * s;
                }
                acc = 0.0f;
            }
        }

        // Shift windows (register renames under full unroll)
        hb0 = hb1; hb1 = hb2; hb2 = hb3; hb3 = h4;
        #pragma unroll
        for (int c = 0; c < 6; c++) { w0[c] = w1[c]; w1[c] = w2[c]; }
    }
}

extern "C" void kernel_launch(void* const* d_in, const int* in_sizes, int n_in,
                              void* d_out, int out_size)
{
    const float* in = (const float*)d_in[0];
    float* out = (float*)d_out;

    // 8 col tiles (4 warps per block) x 34 row strips x 16 batch
    dim3 grid(2, 34, 16);                    // 1088 blocks of 128 threads
    EdgeGuidance_47313359733145_kernel<<<grid, 128>>>(in, out);
}